// round 8
// baseline (speedup 1.0000x reference)
#include <cuda_runtime.h>

typedef unsigned long long ull;

#define NEXPERTS 64
#define S_MAX    8192
#define ZBLK     44
#define ZSMEM    221184   // 216KB: forces SM-exclusive zero blocks (216+35KB > 228KB)

// static scratch (no allocations allowed)
__device__ int   g_idx[S_MAX];
__device__ float g_gate[S_MAX];
__device__ float g_me_partial[(S_MAX / 64) * NEXPERTS];  // per-gemm-block gate sums
__device__ int   g_cnt[(S_MAX / 512) * NEXPERTS];        // per-chunk expert counts
__device__ int   g_base[(S_MAX / 512) * NEXPERTS];       // exclusive prefix per chunk
__device__ int   g_rank[S_MAX];                          // rank within chunk
__device__ float g_laux;

__device__ __forceinline__ ull pack2(float lo, float hi) {
    ull r; asm("mov.b64 %0, {%1, %2};" : "=l"(r) : "f"(lo), "f"(hi)); return r;
}
__device__ __forceinline__ void ffma2(ull& d, ull a, ull b) {
    asm("fma.rn.f32x2 %0, %1, %2, %0;" : "+l"(d) : "l"(a), "l"(b));
}
__device__ __forceinline__ void fadd2(ull& d, ull a) {
    asm("add.rn.f32x2 %0, %0, %1;" : "+l"(d) : "l"(a));
}
__device__ __forceinline__ float2 unpack2(ull v) {
    float2 r; asm("mov.b64 {%0, %1}, %2;" : "=f"(r.x), "=f"(r.y) : "l"(v)); return r;
}

// ---------------------------------------------------------------------------
// Zero-fill (forked branch). Huge unused dynamic smem -> one block per SM and
// NO co-residency with gemm blocks (keeps their L1tex/LSU queues clean).
// 44 SM-exclusive blocks stream STG.128 at DRAM-limited rate.
// ---------------------------------------------------------------------------
__global__ __launch_bounds__(256) void zero_fill(float4* __restrict__ o4, size_t n4,
                                                 float* __restrict__ o, size_t osz) {
    extern __shared__ float dummy[];   // intentionally unused (occupancy control)
    const float4 z = make_float4(0.f, 0.f, 0.f, 0.f);
    const size_t stride = (size_t)gridDim.x * 256;
    size_t i = (size_t)blockIdx.x * 256 + threadIdx.x;
    for (; i + 7 * stride < n4; i += 8 * stride) {
        o4[i]              = z;
        o4[i + stride]     = z;
        o4[i + 2 * stride] = z;
        o4[i + 3 * stride] = z;
        o4[i + 4 * stride] = z;
        o4[i + 5 * stride] = z;
        o4[i + 6 * stride] = z;
        o4[i + 7 * stride] = z;
    }
    for (; i < n4; i += stride) o4[i] = z;
    if (blockIdx.x == 0 && threadIdx.x == 0)
        for (size_t t = n4 * 4; t < osz; ++t) o[t] = 0.f;
    if (threadIdx.x == 0) dummy[0] = 0.f;   // keep the smem request alive
}

// ---------------------------------------------------------------------------
// Kernel 1: logits = x @ wg^T per 64-token tile + fused softmax/argmax.
// 256 threads = 2 k-split halves of 128 (micro 8 tok x 4 exp each); halves
// process k 0..15 / 16..31 of each 32-k tile -> 2 warps/SMSP for latency
// hiding; f32x2 partial reduce in epilogue via a DEDICATED 16KB smem buffer
// (round-7 bug: partials overflowed the aliased As/Bs region).
// ---------------------------------------------------------------------------
__global__ __launch_bounds__(256) void gemm_softmax(const float* __restrict__ x,
                                                    const float* __restrict__ wg,
                                                    int D, int S) {
    __shared__ __align__(16) float sm[64 * 68];   // As[32][68]+Bs[32][68] -> Ls[64][68]
    __shared__ __align__(16) ull  partial[128][16];  // k-split partial accumulators
    __shared__ float sm_m[64], sm_inv[64], red4[4][64];
    float (*As)[68] = (float(*)[68])sm;
    float (*Bs)[68] = (float(*)[68])(sm + 32 * 68);
    float (*Ls)[68] = (float(*)[68])sm;

    const int tid  = threadIdx.x;
    const int g    = tid >> 7;         // k-split half
    const int tid2 = tid & 127;
    const int ty   = tid2 >> 4;        // 0..7  -> tokens ty*8 .. ty*8+7
    const int tx   = tid2 & 15;        // 0..15 -> experts tx*4 .. tx*4+3
    const int s0   = blockIdx.x * 64;

    // loader geometry: i = tid + r*256 (r=0..1) -> row=i>>3 (0..63), k4=(i&7)*4
    int rowr[2], k4r[2];
    const float *xp[2], *wp[2];
#pragma unroll
    for (int r = 0; r < 2; ++r) {
        int i = tid + r * 256;
        rowr[r] = i >> 3; k4r[r] = (i & 7) << 2;
        xp[r] = x  + (size_t)(s0 + rowr[r]) * D + k4r[r];
        wp[r] = wg + (size_t)rowr[r] * D + k4r[r];
    }

    ull acc[4][4];
#pragma unroll
    for (int i = 0; i < 4; ++i)
#pragma unroll
        for (int j = 0; j < 4; ++j) acc[i][j] = 0ull;

    float4 pa[2], pb[2];
#pragma unroll
    for (int r = 0; r < 2; ++r) { pa[r] = *(const float4*)(xp[r]); pb[r] = *(const float4*)(wp[r]); }

    for (int kt = 0; kt < D; kt += 32) {
#pragma unroll
        for (int r = 0; r < 2; ++r) {
            int row = rowr[r], k4 = k4r[r];
            As[k4 + 0][row] = pa[r].x; As[k4 + 1][row] = pa[r].y;
            As[k4 + 2][row] = pa[r].z; As[k4 + 3][row] = pa[r].w;
            Bs[k4 + 0][row] = pb[r].x; Bs[k4 + 1][row] = pb[r].y;
            Bs[k4 + 2][row] = pb[r].z; Bs[k4 + 3][row] = pb[r].w;
        }
        __syncthreads();
        if (kt + 32 < D) {
#pragma unroll
            for (int r = 0; r < 2; ++r) {
                pa[r] = *(const float4*)(xp[r] + kt + 32);
                pb[r] = *(const float4*)(wp[r] + kt + 32);
            }
        }
#pragma unroll
        for (int k = 0; k < 16; ++k) {
            const int kk = k + g * 16;
            ulonglong2 A0 = *(const ulonglong2*)&As[kk][ty * 8];
            ulonglong2 A1 = *(const ulonglong2*)&As[kk][ty * 8 + 4];
            ull a0 = A0.x, a1 = A0.y, a2 = A1.x, a3 = A1.y;   // 8 tokens (4 pairs)
            float4 bv = *(const float4*)&Bs[kk][tx * 4];
            ull b0 = pack2(bv.x, bv.x), b1 = pack2(bv.y, bv.y);
            ull b2 = pack2(bv.z, bv.z), b3 = pack2(bv.w, bv.w);
            ffma2(acc[0][0], a0, b0); ffma2(acc[0][1], a0, b1);
            ffma2(acc[0][2], a0, b2); ffma2(acc[0][3], a0, b3);
            ffma2(acc[1][0], a1, b0); ffma2(acc[1][1], a1, b1);
            ffma2(acc[1][2], a1, b2); ffma2(acc[1][3], a1, b3);
            ffma2(acc[2][0], a2, b0); ffma2(acc[2][1], a2, b1);
            ffma2(acc[2][2], a2, b2); ffma2(acc[2][3], a2, b3);
            ffma2(acc[3][0], a3, b0); ffma2(acc[3][1], a3, b1);
            ffma2(acc[3][2], a3, b2); ffma2(acc[3][3], a3, b3);
        }
        __syncthreads();
    }

    // k-split reduce: half g=1 parks partials in smem, half g=0 accumulates
    if (g == 1) {
#pragma unroll
        for (int i = 0; i < 4; ++i)
#pragma unroll
            for (int j = 0; j < 4; ++j)
                partial[tid2][i * 4 + j] = acc[i][j];
    }
    __syncthreads();
    if (g == 0) {
#pragma unroll
        for (int i = 0; i < 4; ++i)
#pragma unroll
            for (int j = 0; j < 4; ++j)
                fadd2(acc[i][j], partial[tid2][i * 4 + j]);
    }
    __syncthreads();

    // dump logit tile into smem (As/Bs dead now)
    if (g == 0) {
#pragma unroll
        for (int i = 0; i < 4; ++i) {
            float2 c0 = unpack2(acc[i][0]);
            float2 c1 = unpack2(acc[i][1]);
            float2 c2 = unpack2(acc[i][2]);
            float2 c3 = unpack2(acc[i][3]);
            int t0 = ty * 8 + 2 * i;
            *(float4*)&Ls[t0][tx * 4]     = make_float4(c0.x, c1.x, c2.x, c3.x);
            *(float4*)&Ls[t0 + 1][tx * 4] = make_float4(c0.y, c1.y, c2.y, c3.y);
        }
    }
    __syncthreads();

    // per-token softmax + argmax (first max wins = jnp.argmax)
    if (tid < 64) {
        float m = -1e30f; int ix = 0;
#pragma unroll 8
        for (int e = 0; e < 64; ++e) {
            float v = Ls[tid][e];
            if (v > m) { m = v; ix = e; }
        }
        float ssum = 0.f;
#pragma unroll 8
        for (int e = 0; e < 64; ++e) ssum += expf(Ls[tid][e] - m);
        float inv = 1.0f / ssum;
        g_idx[s0 + tid]  = ix;
        g_gate[s0 + tid] = inv;
        sm_m[tid] = m; sm_inv[tid] = inv;
    }
    __syncthreads();

    // per-block me partials: me_e += sum_t softmax(l)[t][e]
    {
        const int e = tid & 63, q = tid >> 6;     // q: 0..3, 16 tokens each
        float mp = 0.f;
#pragma unroll
        for (int t = q * 16; t < q * 16 + 16; ++t)
            mp += expf(Ls[t][e] - sm_m[t]) * sm_inv[t];
        red4[q][e] = mp;
    }
    __syncthreads();
    if (tid < 64)
        g_me_partial[(size_t)blockIdx.x * 64 + tid] =
            red4[0][tid] + red4[1][tid] + red4[2][tid] + red4[3][tid];
}

// ---------------------------------------------------------------------------
// Kernel 2: per-512-token chunk: warp-ballot ranks + per-chunk expert counts.
// ---------------------------------------------------------------------------
__global__ __launch_bounds__(512) void hist_rank() {
    __shared__ int hist[16][64];
    const int tid  = threadIdx.x;
    const int lane = tid & 31;
    const int warp = tid >> 5;
    const int s = blockIdx.x * 512 + tid;

    hist[tid >> 6][tid & 63] = 0;
    ((int*)hist)[512 + tid] = 0;
    __syncthreads();

    const int e = g_idx[s];
    unsigned mask = __match_any_sync(0xffffffffu, e);
    int inrank = __popc(mask & ((1u << lane) - 1));
    int cnt    = __popc(mask);
    if (inrank == 0) hist[warp][e] = cnt;
    __syncthreads();

    if (tid < 64) {            // exclusive prefix over the 16 warps, per expert
        int run = 0;
#pragma unroll
        for (int w = 0; w < 16; ++w) {
            int t = hist[w][tid]; hist[w][tid] = run; run += t;
        }
        g_cnt[blockIdx.x * 64 + tid] = run;
    }
    __syncthreads();
    g_rank[s] = hist[warp][e] + inrank;
}

// ---------------------------------------------------------------------------
// Kernel 3 (tiny, 1 block): chunk prefix per expert + l_aux.
// ---------------------------------------------------------------------------
__global__ __launch_bounds__(1024) void prefix_laux(int S, int nblk, int nchunks) {
    __shared__ float red[16][64];
    __shared__ float prod[64];
    const int tid = threadIdx.x;
    const int e = tid & 63, p = tid >> 6;   // p: 0..15

    float mp = 0.f;
    for (int b = p; b < nblk; b += 16) mp += g_me_partial[(size_t)b * 64 + e];
    red[p][e] = mp;

    if (tid < 64) {
        int run = 0;
        for (int c = 0; c < nchunks; ++c) {
            int t = g_cnt[c * 64 + tid];
            g_base[c * 64 + tid] = run;
            run += t;
        }
        prod[tid] = (float)run / (float)S;   // ce (pre-drop counts)
    }
    __syncthreads();
    if (tid < 64) {
        float me = 0.f;
#pragma unroll
        for (int q = 0; q < 16; ++q) me += red[q][tid];
        prod[tid] *= me / (float)S;
    }
    __syncthreads();
    if (tid == 0) {
        float sum = 0.f;
        for (int ee = 0; ee < 64; ++ee) sum += prod[ee];
        g_laux = sum * (float)NEXPERTS;      // mean(me*ce)*E^2 = sum*E
    }
}

// ---------------------------------------------------------------------------
// Kernel 4: sparse scatter into the (zeroed) output. Runs after the join.
// ---------------------------------------------------------------------------
__global__ void scatter_out(float* __restrict__ out, int S, int C,
                            long long comb_off, long long disp_off, int write_aux) {
    int s = blockIdx.x * blockDim.x + threadIdx.x;
    if (s == 0 && write_aux) out[0] = g_laux;
    if (s < S) {
        int e = g_idx[s];
        int r = g_base[(s >> 9) * 64 + e] + g_rank[s];
        if (r < C) {
            size_t pos = ((size_t)s * NEXPERTS + e) * (size_t)C + r;
            out[(size_t)comb_off + pos] = g_gate[s];
            if (disp_off >= 0)
                out[(size_t)disp_off + pos] = 1.0f;
        }
    }
}

extern "C" void kernel_launch(void* const* d_in, const int* in_sizes, int n_in,
                              void* d_out, int out_size) {
    const float* x  = (const float*)d_in[0];
    const float* wg = (const float*)d_in[1];
    const int D = in_sizes[1] / NEXPERTS;
    const int S = in_sizes[0] / D;
    const int C = (S + NEXPERTS - 1) / NEXPERTS;   // capacity_factor = 1.0
    const size_t SEC = (size_t)S * NEXPERTS * C;
    const size_t osz = (size_t)out_size;

    // output layout: [l_aux(1)][combine(SEC)][dispatch(SEC)] when sizes match
    long long comb = 0, disp = -1; int aux = 0;
    if (osz >= 2 * SEC + 1)      { aux = 1; comb = 1; disp = 1 + (long long)SEC; }
    else if (osz >= 2 * SEC)     { comb = 0; disp = (long long)SEC; }

    const size_t n4 = osz >> 2;

    cudaFuncSetAttribute(zero_fill, cudaFuncAttributeMaxDynamicSharedMemorySize, ZSMEM);

    cudaStream_t s1; cudaStreamCreate(&s1);
    cudaEvent_t ef, ej;
    cudaEventCreateWithFlags(&ef, cudaEventDisableTiming);
    cudaEventCreateWithFlags(&ej, cudaEventDisableTiming);

    cudaEventRecord(ef, 0);

    // branch B FIRST (claims its SMs): SM-exclusive zero-fill of d_out
    cudaStreamWaitEvent(s1, ef, 0);
    zero_fill<<<ZBLK, 256, ZSMEM, s1>>>((float4*)d_out, n4, (float*)d_out, osz);
    cudaEventRecord(ej, s1);

    // branch A (main stream): compute chain on scratch, on the remaining SMs
    gemm_softmax<<<S / 64, 256>>>(x, wg, D, S);
    hist_rank<<<S / 512, 512>>>();
    prefix_laux<<<1, 1024>>>(S, S / 64, S / 512);

    cudaStreamWaitEvent(0, ej, 0);                           // join
    scatter_out<<<(S + 255) / 256, 256>>>((float*)d_out, S, C, comb, disp, aux);
    // s1/ef/ej intentionally not destroyed: kernel_launch runs only a handful
    // of times (correctness + capture); destroying capture-referenced objects
    // mid-capture is unsafe.
}

// round 9
// speedup vs baseline: 1.1684x; 1.1684x over previous
#include <cuda_runtime.h>
#include <cstdint>

typedef unsigned long long ull;

#define NEXPERTS 64
#define S_MAX    8192
#define TBLK     128        // TMA zero-fill blocks
#define TCHUNK   65536      // bytes per bulk store (= smem buffer size)

// static scratch (no allocations allowed)
__device__ int   g_idx[S_MAX];
__device__ float g_gate[S_MAX];
__device__ float g_me_partial[(S_MAX / 64) * NEXPERTS];  // per-gemm-block gate sums
__device__ int   g_cnt[(S_MAX / 512) * NEXPERTS];        // per-chunk expert counts
__device__ int   g_base[(S_MAX / 512) * NEXPERTS];       // exclusive prefix per chunk
__device__ int   g_rank[S_MAX];                          // rank within chunk
__device__ float g_laux;

__device__ __forceinline__ ull pack2(float lo, float hi) {
    ull r; asm("mov.b64 %0, {%1, %2};" : "=l"(r) : "f"(lo), "f"(hi)); return r;
}
__device__ __forceinline__ void ffma2(ull& d, ull a, ull b) {
    asm("fma.rn.f32x2 %0, %1, %2, %0;" : "+l"(d) : "l"(a), "l"(b));
}
__device__ __forceinline__ void fadd2(ull& d, ull a) {
    asm("add.rn.f32x2 %0, %0, %1;" : "+l"(d) : "l"(a));
}
__device__ __forceinline__ float2 unpack2(ull v) {
    float2 r; asm("mov.b64 {%0, %1}, %2;" : "=f"(r.x), "=f"(r.y) : "l"(v)); return r;
}
__device__ __forceinline__ uint32_t smem_u32(const void* p) {
    uint32_t a;
    asm("{ .reg .u64 t; cvta.to.shared.u64 t, %1; cvt.u32.u64 %0, t; }" : "=r"(a) : "l"(p));
    return a;
}

// ---------------------------------------------------------------------------
// Zero-fill via TMA bulk stores (forked branch). The 537MB of zeros stream
// through the TMA engines (cp.async.bulk shared->global), costing essentially
// no SM issue slots — unlike STG.128, which is LSU-bound at ~43 B/cyc/SM and
// therefore needs every SM (rounds 6/8 finding). GEMM blocks co-reside and
// keep the fma pipes busy while TMA saturates DRAM write.
// ---------------------------------------------------------------------------
__global__ __launch_bounds__(256) void zero_tma(char* __restrict__ out, size_t bytes) {
    extern __shared__ __align__(128) float4 zbuf[];   // TCHUNK bytes, stays zero
    const int tid = threadIdx.x;
    for (int i = tid; i < TCHUNK / 16; i += 256)
        zbuf[i] = make_float4(0.f, 0.f, 0.f, 0.f);
    asm volatile("fence.proxy.async.shared::cta;" ::: "memory");
    __syncthreads();

    const size_t n16 = bytes & ~(size_t)15;
    if (tid == 0) {
        const uint32_t saddr = smem_u32(zbuf);
        const size_t nchunk = (n16 + TCHUNK - 1) / TCHUNK;
        for (size_t c = blockIdx.x; c < nchunk; c += gridDim.x) {
            size_t off = c * (size_t)TCHUNK;
            uint32_t sz = (uint32_t)((n16 - off < TCHUNK) ? (n16 - off) : TCHUNK);
            asm volatile(
                "cp.async.bulk.global.shared::cta.bulk_group [%0], [%1], %2;"
                :: "l"(out + off), "r"(saddr), "r"(sz) : "memory");
        }
        asm volatile("cp.async.bulk.commit_group;" ::: "memory");
        asm volatile("cp.async.bulk.wait_group 0;" ::: "memory");
    }
    // tail bytes (< 16): plain stores
    if (blockIdx.x == 0) {
        size_t t = n16 + (size_t)tid * 4;
        if (t < bytes) *(float*)(out + t) = 0.f;
    }
    __syncthreads();
}

// ---------------------------------------------------------------------------
// Kernel 1: logits = x @ wg^T per 64-token tile + fused softmax/argmax.
// 256 threads = 2 k-split halves of 128 (micro 8 tok x 4 exp each);
// f32x2 partial reduce via dedicated smem buffer.
// ---------------------------------------------------------------------------
__global__ __launch_bounds__(256) void gemm_softmax(const float* __restrict__ x,
                                                    const float* __restrict__ wg,
                                                    int D, int S) {
    __shared__ __align__(16) float sm[64 * 68];   // As[32][68]+Bs[32][68] -> Ls[64][68]
    __shared__ __align__(16) ull  partial[128][16];  // k-split partial accumulators
    __shared__ float sm_m[64], sm_inv[64], red4[4][64];
    float (*As)[68] = (float(*)[68])sm;
    float (*Bs)[68] = (float(*)[68])(sm + 32 * 68);
    float (*Ls)[68] = (float(*)[68])sm;

    const int tid  = threadIdx.x;
    const int g    = tid >> 7;         // k-split half
    const int tid2 = tid & 127;
    const int ty   = tid2 >> 4;        // 0..7  -> tokens ty*8 .. ty*8+7
    const int tx   = tid2 & 15;        // 0..15 -> experts tx*4 .. tx*4+3
    const int s0   = blockIdx.x * 64;

    int rowr[2], k4r[2];
    const float *xp[2], *wp[2];
#pragma unroll
    for (int r = 0; r < 2; ++r) {
        int i = tid + r * 256;
        rowr[r] = i >> 3; k4r[r] = (i & 7) << 2;
        xp[r] = x  + (size_t)(s0 + rowr[r]) * D + k4r[r];
        wp[r] = wg + (size_t)rowr[r] * D + k4r[r];
    }

    ull acc[4][4];
#pragma unroll
    for (int i = 0; i < 4; ++i)
#pragma unroll
        for (int j = 0; j < 4; ++j) acc[i][j] = 0ull;

    float4 pa[2], pb[2];
#pragma unroll
    for (int r = 0; r < 2; ++r) { pa[r] = *(const float4*)(xp[r]); pb[r] = *(const float4*)(wp[r]); }

    for (int kt = 0; kt < D; kt += 32) {
#pragma unroll
        for (int r = 0; r < 2; ++r) {
            int row = rowr[r], k4 = k4r[r];
            As[k4 + 0][row] = pa[r].x; As[k4 + 1][row] = pa[r].y;
            As[k4 + 2][row] = pa[r].z; As[k4 + 3][row] = pa[r].w;
            Bs[k4 + 0][row] = pb[r].x; Bs[k4 + 1][row] = pb[r].y;
            Bs[k4 + 2][row] = pb[r].z; Bs[k4 + 3][row] = pb[r].w;
        }
        __syncthreads();
        if (kt + 32 < D) {
#pragma unroll
            for (int r = 0; r < 2; ++r) {
                pa[r] = *(const float4*)(xp[r] + kt + 32);
                pb[r] = *(const float4*)(wp[r] + kt + 32);
            }
        }
#pragma unroll
        for (int k = 0; k < 16; ++k) {
            const int kk = k + g * 16;
            ulonglong2 A0 = *(const ulonglong2*)&As[kk][ty * 8];
            ulonglong2 A1 = *(const ulonglong2*)&As[kk][ty * 8 + 4];
            ull a0 = A0.x, a1 = A0.y, a2 = A1.x, a3 = A1.y;   // 8 tokens (4 pairs)
            float4 bv = *(const float4*)&Bs[kk][tx * 4];
            ull b0 = pack2(bv.x, bv.x), b1 = pack2(bv.y, bv.y);
            ull b2 = pack2(bv.z, bv.z), b3 = pack2(bv.w, bv.w);
            ffma2(acc[0][0], a0, b0); ffma2(acc[0][1], a0, b1);
            ffma2(acc[0][2], a0, b2); ffma2(acc[0][3], a0, b3);
            ffma2(acc[1][0], a1, b0); ffma2(acc[1][1], a1, b1);
            ffma2(acc[1][2], a1, b2); ffma2(acc[1][3], a1, b3);
            ffma2(acc[2][0], a2, b0); ffma2(acc[2][1], a2, b1);
            ffma2(acc[2][2], a2, b2); ffma2(acc[2][3], a2, b3);
            ffma2(acc[3][0], a3, b0); ffma2(acc[3][1], a3, b1);
            ffma2(acc[3][2], a3, b2); ffma2(acc[3][3], a3, b3);
        }
        __syncthreads();
    }

    // k-split reduce
    if (g == 1) {
#pragma unroll
        for (int i = 0; i < 4; ++i)
#pragma unroll
            for (int j = 0; j < 4; ++j)
                partial[tid2][i * 4 + j] = acc[i][j];
    }
    __syncthreads();
    if (g == 0) {
#pragma unroll
        for (int i = 0; i < 4; ++i)
#pragma unroll
            for (int j = 0; j < 4; ++j)
                fadd2(acc[i][j], partial[tid2][i * 4 + j]);
    }
    __syncthreads();

    // dump logit tile into smem (As/Bs dead now)
    if (g == 0) {
#pragma unroll
        for (int i = 0; i < 4; ++i) {
            float2 c0 = unpack2(acc[i][0]);
            float2 c1 = unpack2(acc[i][1]);
            float2 c2 = unpack2(acc[i][2]);
            float2 c3 = unpack2(acc[i][3]);
            int t0 = ty * 8 + 2 * i;
            *(float4*)&Ls[t0][tx * 4]     = make_float4(c0.x, c1.x, c2.x, c3.x);
            *(float4*)&Ls[t0 + 1][tx * 4] = make_float4(c0.y, c1.y, c2.y, c3.y);
        }
    }
    __syncthreads();

    // per-token softmax + argmax (first max wins = jnp.argmax)
    if (tid < 64) {
        float m = -1e30f; int ix = 0;
#pragma unroll 8
        for (int e = 0; e < 64; ++e) {
            float v = Ls[tid][e];
            if (v > m) { m = v; ix = e; }
        }
        float ssum = 0.f;
#pragma unroll 8
        for (int e = 0; e < 64; ++e) ssum += expf(Ls[tid][e] - m);
        float inv = 1.0f / ssum;
        g_idx[s0 + tid]  = ix;
        g_gate[s0 + tid] = inv;
        sm_m[tid] = m; sm_inv[tid] = inv;
    }
    __syncthreads();

    // per-block me partials
    {
        const int e = tid & 63, q = tid >> 6;     // q: 0..3, 16 tokens each
        float mp = 0.f;
#pragma unroll
        for (int t = q * 16; t < q * 16 + 16; ++t)
            mp += expf(Ls[t][e] - sm_m[t]) * sm_inv[t];
        red4[q][e] = mp;
    }
    __syncthreads();
    if (tid < 64)
        g_me_partial[(size_t)blockIdx.x * 64 + tid] =
            red4[0][tid] + red4[1][tid] + red4[2][tid] + red4[3][tid];
}

// ---------------------------------------------------------------------------
// Kernel 2: per-512-token chunk: warp-ballot ranks + per-chunk expert counts.
// ---------------------------------------------------------------------------
__global__ __launch_bounds__(512) void hist_rank() {
    __shared__ int hist[16][64];
    const int tid  = threadIdx.x;
    const int lane = tid & 31;
    const int warp = tid >> 5;
    const int s = blockIdx.x * 512 + tid;

    hist[tid >> 6][tid & 63] = 0;
    ((int*)hist)[512 + tid] = 0;
    __syncthreads();

    const int e = g_idx[s];
    unsigned mask = __match_any_sync(0xffffffffu, e);
    int inrank = __popc(mask & ((1u << lane) - 1));
    int cnt    = __popc(mask);
    if (inrank == 0) hist[warp][e] = cnt;
    __syncthreads();

    if (tid < 64) {
        int run = 0;
#pragma unroll
        for (int w = 0; w < 16; ++w) {
            int t = hist[w][tid]; hist[w][tid] = run; run += t;
        }
        g_cnt[blockIdx.x * 64 + tid] = run;
    }
    __syncthreads();
    g_rank[s] = hist[warp][e] + inrank;
}

// ---------------------------------------------------------------------------
// Kernel 3 (tiny, 1 block): chunk prefix per expert + l_aux.
// ---------------------------------------------------------------------------
__global__ __launch_bounds__(1024) void prefix_laux(int S, int nblk, int nchunks) {
    __shared__ float red[16][64];
    __shared__ float prod[64];
    const int tid = threadIdx.x;
    const int e = tid & 63, p = tid >> 6;   // p: 0..15

    float mp = 0.f;
    for (int b = p; b < nblk; b += 16) mp += g_me_partial[(size_t)b * 64 + e];
    red[p][e] = mp;

    if (tid < 64) {
        int run = 0;
        for (int c = 0; c < nchunks; ++c) {
            int t = g_cnt[c * 64 + tid];
            g_base[c * 64 + tid] = run;
            run += t;
        }
        prod[tid] = (float)run / (float)S;   // ce (pre-drop counts)
    }
    __syncthreads();
    if (tid < 64) {
        float me = 0.f;
#pragma unroll
        for (int q = 0; q < 16; ++q) me += red[q][tid];
        prod[tid] *= me / (float)S;
    }
    __syncthreads();
    if (tid == 0) {
        float sum = 0.f;
        for (int ee = 0; ee < 64; ++ee) sum += prod[ee];
        g_laux = sum * (float)NEXPERTS;      // mean(me*ce)*E^2 = sum*E
    }
}

// ---------------------------------------------------------------------------
// Kernel 4: sparse scatter into the (zeroed) output. Runs after the join.
// ---------------------------------------------------------------------------
__global__ void scatter_out(float* __restrict__ out, int S, int C,
                            long long comb_off, long long disp_off, int write_aux) {
    int s = blockIdx.x * blockDim.x + threadIdx.x;
    if (s == 0 && write_aux) out[0] = g_laux;
    if (s < S) {
        int e = g_idx[s];
        int r = g_base[(s >> 9) * 64 + e] + g_rank[s];
        if (r < C) {
            size_t pos = ((size_t)s * NEXPERTS + e) * (size_t)C + r;
            out[(size_t)comb_off + pos] = g_gate[s];
            if (disp_off >= 0)
                out[(size_t)disp_off + pos] = 1.0f;
        }
    }
}

extern "C" void kernel_launch(void* const* d_in, const int* in_sizes, int n_in,
                              void* d_out, int out_size) {
    const float* x  = (const float*)d_in[0];
    const float* wg = (const float*)d_in[1];
    const int D = in_sizes[1] / NEXPERTS;
    const int S = in_sizes[0] / D;
    const int C = (S + NEXPERTS - 1) / NEXPERTS;   // capacity_factor = 1.0
    const size_t SEC = (size_t)S * NEXPERTS * C;
    const size_t osz = (size_t)out_size;

    long long comb = 0, disp = -1; int aux = 0;
    if (osz >= 2 * SEC + 1)      { aux = 1; comb = 1; disp = 1 + (long long)SEC; }
    else if (osz >= 2 * SEC)     { comb = 0; disp = (long long)SEC; }

    cudaFuncSetAttribute(zero_tma, cudaFuncAttributeMaxDynamicSharedMemorySize, TCHUNK);

    cudaStream_t s1; cudaStreamCreate(&s1);
    cudaEvent_t ef, ej;
    cudaEventCreateWithFlags(&ef, cudaEventDisableTiming);
    cudaEventCreateWithFlags(&ej, cudaEventDisableTiming);

    cudaEventRecord(ef, 0);

    // branch B: TMA-engine zero-fill of d_out (no LSU cost, co-resident)
    cudaStreamWaitEvent(s1, ef, 0);
    zero_tma<<<TBLK, 256, TCHUNK, s1>>>((char*)d_out, osz * sizeof(float));
    cudaEventRecord(ej, s1);

    // branch A (main stream): compute chain on scratch
    gemm_softmax<<<S / 64, 256>>>(x, wg, D, S);
    hist_rank<<<S / 512, 512>>>();
    prefix_laux<<<1, 1024>>>(S, S / 64, S / 512);

    cudaStreamWaitEvent(0, ej, 0);                           // join
    scatter_out<<<(S + 255) / 256, 256>>>((float*)d_out, S, C, comb, disp, aux);
    // s1/ef/ej intentionally not destroyed (capture-referenced).
}

// round 10
// speedup vs baseline: 1.3725x; 1.1746x over previous
#include <cuda_runtime.h>
#include <cstdint>

typedef unsigned long long ull;

#define NEXPERTS 64
#define S_MAX    8192
#define ZCHUNK   16384      // bytes per bulk store (= smem zero buffer size)

// static scratch (no allocations allowed)
__device__ int   g_idx[S_MAX];
__device__ float g_gate[S_MAX];
__device__ float g_me_partial[(S_MAX / 64) * NEXPERTS];  // per-gemm-block gate sums
__device__ int   g_cnt[(S_MAX / 512) * NEXPERTS];        // per-chunk expert counts
__device__ int   g_base[(S_MAX / 512) * NEXPERTS];       // exclusive prefix per chunk
__device__ int   g_rank[S_MAX];                          // rank within chunk
__device__ float g_laux;

__device__ __forceinline__ ull pack2(float lo, float hi) {
    ull r; asm("mov.b64 %0, {%1, %2};" : "=l"(r) : "f"(lo), "f"(hi)); return r;
}
__device__ __forceinline__ void ffma2(ull& d, ull a, ull b) {
    asm("fma.rn.f32x2 %0, %1, %2, %0;" : "+l"(d) : "l"(a), "l"(b));
}
__device__ __forceinline__ void fadd2(ull& d, ull a) {
    asm("add.rn.f32x2 %0, %0, %1;" : "+l"(d) : "l"(a));
}
__device__ __forceinline__ float2 unpack2(ull v) {
    float2 r; asm("mov.b64 {%0, %1}, %2;" : "=f"(r.x), "=f"(r.y) : "l"(v)); return r;
}
__device__ __forceinline__ uint32_t smem_u32(const void* p) {
    uint32_t a;
    asm("{ .reg .u64 t; cvta.to.shared.u64 t, %1; cvt.u32.u64 %0, t; }" : "=r"(a) : "l"(p));
    return a;
}
// named barrier for the 8 gemm warps only (TMA warp never joins)
#define GSYNC() asm volatile("bar.sync 1, 256;" ::: "memory")

// ---------------------------------------------------------------------------
// Kernel 1 (warp-specialized): 288 threads.
//   warps 0-7 (tid 0..255): logits = x @ wg^T per 64-token tile (2-way k-split,
//     micro 8 tok x 4 exp, FFMA2) + fused softmax/argmax epilogue, synced by
//     named barrier 1.
//   warp 8 (tid 256..287): zeroes a 16KB smem buffer and TMA-bulk-stores it
//     over this block's slice of d_out (537MB total across 128 blocks). TMA
//     consumes no SM issue slots -> full overlap with the fma-bound gemm.
// Kernel completion (wait_group 0) makes the zeros visible to later kernels.
// ---------------------------------------------------------------------------
__global__ __launch_bounds__(288) void gemm_zero_softmax(const float* __restrict__ x,
                                                         const float* __restrict__ wg,
                                                         int D, int S,
                                                         char* __restrict__ zout,
                                                         size_t zbytes) {
    __shared__ __align__(16) float sm[64 * 68];     // As[32][68]+Bs[32][68] -> Ls[64][68]
    __shared__ __align__(16) ull  partial[128][16]; // k-split partial accumulators
    __shared__ __align__(128) float4 zbuf[ZCHUNK / 16];
    __shared__ float sm_m[64], sm_inv[64], red4[4][64];
    float (*As)[68] = (float(*)[68])sm;
    float (*Bs)[68] = (float(*)[68])(sm + 32 * 68);
    float (*Ls)[68] = (float(*)[68])sm;

    const int tid = threadIdx.x;

    if (tid >= 256) {
        // ---------------- TMA zero warp ----------------
        const int lane = tid - 256;
        const float4 z4 = make_float4(0.f, 0.f, 0.f, 0.f);
        for (int i = lane; i < ZCHUNK / 16; i += 32) zbuf[i] = z4;
        asm volatile("fence.proxy.async.shared::cta;" ::: "memory");
        __syncwarp();

        const size_t n16 = zbytes & ~(size_t)15;
        if (lane == 0) {
            const uint32_t saddr = smem_u32(zbuf);
            const size_t nchunk = (n16 + ZCHUNK - 1) / ZCHUNK;
            for (size_t c = blockIdx.x; c < nchunk; c += gridDim.x) {
                size_t off = c * (size_t)ZCHUNK;
                uint32_t sz = (uint32_t)((n16 - off < ZCHUNK) ? (n16 - off) : ZCHUNK);
                asm volatile(
                    "cp.async.bulk.global.shared::cta.bulk_group [%0], [%1], %2;"
                    :: "l"(zout + off), "r"(saddr), "r"(sz) : "memory");
            }
            asm volatile("cp.async.bulk.commit_group;" ::: "memory");
            asm volatile("cp.async.bulk.wait_group 0;" ::: "memory");
            if (blockIdx.x == 0) {                 // tail bytes (< 16)
                for (size_t t = n16; t < zbytes; t += 4) *(float*)(zout + t) = 0.f;
            }
        }
        return;   // never touches named barrier 1
    }

    // ---------------- GEMM warps (tid 0..255) ----------------
    const int g    = tid >> 7;         // k-split half
    const int tid2 = tid & 127;
    const int ty   = tid2 >> 4;        // 0..7  -> tokens ty*8 .. ty*8+7
    const int tx   = tid2 & 15;        // 0..15 -> experts tx*4 .. tx*4+3
    const int s0   = blockIdx.x * 64;

    int rowr[2], k4r[2];
    const float *xp[2], *wp[2];
#pragma unroll
    for (int r = 0; r < 2; ++r) {
        int i = tid + r * 256;
        rowr[r] = i >> 3; k4r[r] = (i & 7) << 2;
        xp[r] = x  + (size_t)(s0 + rowr[r]) * D + k4r[r];
        wp[r] = wg + (size_t)rowr[r] * D + k4r[r];
    }

    ull acc[4][4];
#pragma unroll
    for (int i = 0; i < 4; ++i)
#pragma unroll
        for (int j = 0; j < 4; ++j) acc[i][j] = 0ull;

    float4 pa[2], pb[2];
#pragma unroll
    for (int r = 0; r < 2; ++r) { pa[r] = *(const float4*)(xp[r]); pb[r] = *(const float4*)(wp[r]); }

    for (int kt = 0; kt < D; kt += 32) {
#pragma unroll
        for (int r = 0; r < 2; ++r) {
            int row = rowr[r], k4 = k4r[r];
            As[k4 + 0][row] = pa[r].x; As[k4 + 1][row] = pa[r].y;
            As[k4 + 2][row] = pa[r].z; As[k4 + 3][row] = pa[r].w;
            Bs[k4 + 0][row] = pb[r].x; Bs[k4 + 1][row] = pb[r].y;
            Bs[k4 + 2][row] = pb[r].z; Bs[k4 + 3][row] = pb[r].w;
        }
        GSYNC();
        if (kt + 32 < D) {
#pragma unroll
            for (int r = 0; r < 2; ++r) {
                pa[r] = *(const float4*)(xp[r] + kt + 32);
                pb[r] = *(const float4*)(wp[r] + kt + 32);
            }
        }
#pragma unroll
        for (int k = 0; k < 16; ++k) {
            const int kk = k + g * 16;
            ulonglong2 A0 = *(const ulonglong2*)&As[kk][ty * 8];
            ulonglong2 A1 = *(const ulonglong2*)&As[kk][ty * 8 + 4];
            ull a0 = A0.x, a1 = A0.y, a2 = A1.x, a3 = A1.y;   // 8 tokens (4 pairs)
            float4 bv = *(const float4*)&Bs[kk][tx * 4];
            ull b0 = pack2(bv.x, bv.x), b1 = pack2(bv.y, bv.y);
            ull b2 = pack2(bv.z, bv.z), b3 = pack2(bv.w, bv.w);
            ffma2(acc[0][0], a0, b0); ffma2(acc[0][1], a0, b1);
            ffma2(acc[0][2], a0, b2); ffma2(acc[0][3], a0, b3);
            ffma2(acc[1][0], a1, b0); ffma2(acc[1][1], a1, b1);
            ffma2(acc[1][2], a1, b2); ffma2(acc[1][3], a1, b3);
            ffma2(acc[2][0], a2, b0); ffma2(acc[2][1], a2, b1);
            ffma2(acc[2][2], a2, b2); ffma2(acc[2][3], a2, b3);
            ffma2(acc[3][0], a3, b0); ffma2(acc[3][1], a3, b1);
            ffma2(acc[3][2], a3, b2); ffma2(acc[3][3], a3, b3);
        }
        GSYNC();
    }

    // k-split reduce: half g=1 parks partials in smem, half g=0 accumulates
    if (g == 1) {
#pragma unroll
        for (int i = 0; i < 4; ++i)
#pragma unroll
            for (int j = 0; j < 4; ++j)
                partial[tid2][i * 4 + j] = acc[i][j];
    }
    GSYNC();
    if (g == 0) {
#pragma unroll
        for (int i = 0; i < 4; ++i)
#pragma unroll
            for (int j = 0; j < 4; ++j)
                fadd2(acc[i][j], partial[tid2][i * 4 + j]);
    }
    GSYNC();

    // dump logit tile into smem (As/Bs dead now)
    if (g == 0) {
#pragma unroll
        for (int i = 0; i < 4; ++i) {
            float2 c0 = unpack2(acc[i][0]);
            float2 c1 = unpack2(acc[i][1]);
            float2 c2 = unpack2(acc[i][2]);
            float2 c3 = unpack2(acc[i][3]);
            int t0 = ty * 8 + 2 * i;
            *(float4*)&Ls[t0][tx * 4]     = make_float4(c0.x, c1.x, c2.x, c3.x);
            *(float4*)&Ls[t0 + 1][tx * 4] = make_float4(c0.y, c1.y, c2.y, c3.y);
        }
    }
    GSYNC();

    // per-token softmax + argmax (first max wins = jnp.argmax)
    if (tid < 64) {
        float m = -1e30f; int ix = 0;
#pragma unroll 8
        for (int e = 0; e < 64; ++e) {
            float v = Ls[tid][e];
            if (v > m) { m = v; ix = e; }
        }
        float ssum = 0.f;
#pragma unroll 8
        for (int e = 0; e < 64; ++e) ssum += expf(Ls[tid][e] - m);
        float inv = 1.0f / ssum;
        g_idx[s0 + tid]  = ix;
        g_gate[s0 + tid] = inv;
        sm_m[tid] = m; sm_inv[tid] = inv;
    }
    GSYNC();

    // per-block me partials: me_e += sum_t softmax(l)[t][e]
    {
        const int e = tid & 63, q = tid >> 6;     // q: 0..3, 16 tokens each
        float mp = 0.f;
#pragma unroll
        for (int t = q * 16; t < q * 16 + 16; ++t)
            mp += expf(Ls[t][e] - sm_m[t]) * sm_inv[t];
        red4[q][e] = mp;
    }
    GSYNC();
    if (tid < 64)
        g_me_partial[(size_t)blockIdx.x * 64 + tid] =
            red4[0][tid] + red4[1][tid] + red4[2][tid] + red4[3][tid];
}

// ---------------------------------------------------------------------------
// Kernel 2: per-512-token chunk: warp-ballot ranks + per-chunk expert counts.
// ---------------------------------------------------------------------------
__global__ __launch_bounds__(512) void hist_rank() {
    __shared__ int hist[16][64];
    const int tid  = threadIdx.x;
    const int lane = tid & 31;
    const int warp = tid >> 5;
    const int s = blockIdx.x * 512 + tid;

    hist[tid >> 6][tid & 63] = 0;
    ((int*)hist)[512 + tid] = 0;
    __syncthreads();

    const int e = g_idx[s];
    unsigned mask = __match_any_sync(0xffffffffu, e);
    int inrank = __popc(mask & ((1u << lane) - 1));
    int cnt    = __popc(mask);
    if (inrank == 0) hist[warp][e] = cnt;
    __syncthreads();

    if (tid < 64) {
        int run = 0;
#pragma unroll
        for (int w = 0; w < 16; ++w) {
            int t = hist[w][tid]; hist[w][tid] = run; run += t;
        }
        g_cnt[blockIdx.x * 64 + tid] = run;
    }
    __syncthreads();
    g_rank[s] = hist[warp][e] + inrank;
}

// ---------------------------------------------------------------------------
// Kernel 3 (tiny, 1 block): chunk prefix per expert + l_aux.
// ---------------------------------------------------------------------------
__global__ __launch_bounds__(1024) void prefix_laux(int S, int nblk, int nchunks) {
    __shared__ float red[16][64];
    __shared__ float prod[64];
    const int tid = threadIdx.x;
    const int e = tid & 63, p = tid >> 6;   // p: 0..15

    float mp = 0.f;
    for (int b = p; b < nblk; b += 16) mp += g_me_partial[(size_t)b * 64 + e];
    red[p][e] = mp;

    if (tid < 64) {
        int run = 0;
        for (int c = 0; c < nchunks; ++c) {
            int t = g_cnt[c * 64 + tid];
            g_base[c * 64 + tid] = run;
            run += t;
        }
        prod[tid] = (float)run / (float)S;   // ce (pre-drop counts)
    }
    __syncthreads();
    if (tid < 64) {
        float me = 0.f;
#pragma unroll
        for (int q = 0; q < 16; ++q) me += red[q][tid];
        prod[tid] *= me / (float)S;
    }
    __syncthreads();
    if (tid == 0) {
        float sum = 0.f;
        for (int ee = 0; ee < 64; ++ee) sum += prod[ee];
        g_laux = sum * (float)NEXPERTS;      // mean(me*ce)*E^2 = sum*E
    }
}

// ---------------------------------------------------------------------------
// Kernel 4: sparse scatter into the (zeroed) output.
// ---------------------------------------------------------------------------
__global__ void scatter_out(float* __restrict__ out, int S, int C,
                            long long comb_off, long long disp_off, int write_aux) {
    int s = blockIdx.x * blockDim.x + threadIdx.x;
    if (s == 0 && write_aux) out[0] = g_laux;
    if (s < S) {
        int e = g_idx[s];
        int r = g_base[(s >> 9) * 64 + e] + g_rank[s];
        if (r < C) {
            size_t pos = ((size_t)s * NEXPERTS + e) * (size_t)C + r;
            out[(size_t)comb_off + pos] = g_gate[s];
            if (disp_off >= 0)
                out[(size_t)disp_off + pos] = 1.0f;
        }
    }
}

extern "C" void kernel_launch(void* const* d_in, const int* in_sizes, int n_in,
                              void* d_out, int out_size) {
    const float* x  = (const float*)d_in[0];
    const float* wg = (const float*)d_in[1];
    const int D = in_sizes[1] / NEXPERTS;
    const int S = in_sizes[0] / D;
    const int C = (S + NEXPERTS - 1) / NEXPERTS;   // capacity_factor = 1.0
    const size_t SEC = (size_t)S * NEXPERTS * C;
    const size_t osz = (size_t)out_size;

    long long comb = 0, disp = -1; int aux = 0;
    if (osz >= 2 * SEC + 1)      { aux = 1; comb = 1; disp = 1 + (long long)SEC; }
    else if (osz >= 2 * SEC)     { comb = 0; disp = (long long)SEC; }

    // One warp-specialized kernel: gemm+softmax on 8 warps, TMA zero-fill of
    // d_out on the 9th. No streams/events needed; kernel completion orders
    // the zeros before the scatter.
    gemm_zero_softmax<<<S / 64, 288>>>(x, wg, D, S,
                                       (char*)d_out, osz * sizeof(float));
    hist_rank<<<S / 512, 512>>>();
    prefix_laux<<<1, 1024>>>(S, S / 64, S / 512);
    scatter_out<<<(S + 255) / 256, 256>>>((float*)d_out, S, C, comb, disp, aux);
}